// round 8
// baseline (speedup 1.0000x reference)
#include <cuda_runtime.h>

// Problem constants (fixed shapes from the reference setup_inputs)
#define Bq   4
#define Tq   512
#define TPq  1024
#define Cq   32
#define Kq   128
#define EPSF 2.2204460492503131e-16f

// Scratch (__device__ globals — no allocation allowed in kernel_launch)
__device__ float g_sp_delta[Cq * Cq];   // softplus(delta)[e][c] + EPS
__device__ float g_sp_mu[Cq];
__device__ float g_probs[Kq];           // p(fine k | coarse ftc[k])
// Prefix table: G[b][j][e][c], j in [0, T]  (8.4 MB, L2-resident)
__device__ float g_table[(size_t)Bq * (Tq + 1) * Cq * Cq];

__device__ __forceinline__ float softplus_f(float x) {
    // log(1 + e^x), fast version (rel err ~1e-6, tol is 1e-3)
    return (x > 0.0f) ? x + __logf(1.0f + __expf(-x))
                      : __logf(1.0f + __expf(x));
}

// ---------------------------------------------------------------------------
// Kernel 1: build causal prefix table + publish prepped parameters.
//   block = (b, e) pair, 512 threads = 16 warps; lane = channel c,
//   warp w owns j-chunk [w*32, (w+1)*32).
//   G[b][j][e][c] = sum over events i<j with type e of pa[e,c]*exp(pd[e,c]*pt_i)
//   Two-pass chunk scan: pass 1 chunk totals, pass 2 write prefix.
//   Side duties (prep):  b==0,wid==0: g_sp_delta row e
//                        block 0, wid 1: g_sp_mu;  wid 2: grouped softmax
// ---------------------------------------------------------------------------
__global__ void __launch_bounds__(512)
table_kernel(const int*   __restrict__ past_event,
             const float* __restrict__ past_time,
             const float* __restrict__ alpha,
             const float* __restrict__ delta,
             const float* __restrict__ mu,
             const float* __restrict__ cf,
             const int*   __restrict__ ftc) {
    int b   = blockIdx.x / Cq;
    int e   = blockIdx.x % Cq;
    int wid = threadIdx.x >> 5;
    int c   = threadIdx.x & 31;

    __shared__ int   s_ev[Tq];
    __shared__ float s_pt[Tq];
    __shared__ float s_chunk[16][Cq];
    __shared__ float s_den[Cq];

    for (int i = threadIdx.x; i < Tq; i += blockDim.x) {
        s_ev[i] = past_event[b * Tq + i];
        s_pt[i] = past_time[b * Tq + i];
    }

    float pa = softplus_f(alpha[e * Cq + c]);
    float pd = softplus_f(delta[e * Cq + c]) + EPSF;

    // ---- side duties (before first __syncthreads, fully parallel) ----
    if (b == 0 && wid == 0) g_sp_delta[e * Cq + c] = pd;
    if (blockIdx.x == 0) {
        if (wid == 1) g_sp_mu[c] = softplus_f(mu[c]);
        if (wid == 2) {
            // grouped softmax over 128 fine logits (max-shift cancels exactly)
            s_den[c] = 0.0f;
            __syncwarp();
            float ev[4]; int fc[4];
            #pragma unroll
            for (int r = 0; r < 4; r++) {
                int k = r * 32 + c;
                ev[r] = __expf(cf[k]);
                fc[r] = ftc[k];
                atomicAdd(&s_den[fc[r]], ev[r]);
            }
            __syncwarp();
            #pragma unroll
            for (int r = 0; r < 4; r++)
                g_probs[r * 32 + c] = ev[r] / s_den[fc[r]];
        }
    }
    __syncthreads();

    const int CHUNK = Tq / 16;          // 32
    int j0 = wid * CHUNK, j1 = j0 + CHUNK;

    // pass 1: chunk totals (s_ev[j]==e is warp-uniform -> exp only on matches)
    float sum = 0.0f;
    for (int j = j0; j < j1; j++)
        if (s_ev[j] == e) sum += pa * __expf(pd * s_pt[j]);
    s_chunk[wid][c] = sum;
    __syncthreads();

    float off = 0.0f;
    #pragma unroll
    for (int w = 0; w < 16; w++) if (w < wid) off += s_chunk[w][c];

    // pass 2: write exclusive prefix
    float* out = g_table + ((size_t)b * (Tq + 1)) * (Cq * Cq) + e * Cq + c;
    float run = off;
    for (int j = j0; j < j1; j++) {
        out[(size_t)j * (Cq * Cq)] = run;
        if (s_ev[j] == e) run += pa * __expf(pd * s_pt[j]);
    }
    if (wid == 15) out[(size_t)Tq * (Cq * Cq)] = run;
}

// ---------------------------------------------------------------------------
// Kernel 2: queries. One warp per query time. No shared memory, no barriers.
//   acc[c] = sp_mu[c] + sum_e exp(-pd[e,c]*t') * G[b][j][e][c]
//   Vectorized: lane l, seg s covers flat idx f = s*128 + 4l of the 32x32
//   (e,c) tile -> e = 4s + (l>>3), c = 4*(l&7)..+3, as one float4.
//   Reduce over e with shfl_xor(8,16) float4 butterfly; redistribute to
//   scalar acc[c] per lane; out[k] = acc[ftc[k]] * p[k] via shuffle gather.
// ---------------------------------------------------------------------------
__global__ void __launch_bounds__(128, 6)
query_kernel(const float* __restrict__ time_tensor,
             const float* __restrict__ past_time,
             const int*   __restrict__ ftc,
             float*       __restrict__ out) {
    int warp_g = (blockIdx.x * blockDim.x + threadIdx.x) >> 5;  // global query id
    int lane   = threadIdx.x & 31;
    int b      = warp_g >> 10;          // / TPq

    float t = time_tensor[warp_g];

    // binary search: j = #{i : t - pt_i > EPS}  (pt non-decreasing).
    // Warp-uniform index -> one broadcast load per step, L1-hot after warmup.
    const float* pt = past_time + b * Tq;
    int lo = 0, hi = Tq;
    while (lo < hi) {
        int mid = (lo + hi) >> 1;
        if (t - __ldg(&pt[mid]) > EPSF) lo = mid + 1; else hi = mid;
    }

    const float4* Grow = reinterpret_cast<const float4*>(
        g_table + ((size_t)(b * (Tq + 1) + lo)) * (Cq * Cq));
    const float4* pd4p = reinterpret_cast<const float4*>(g_sp_delta);

    float4 acc4 = make_float4(0.f, 0.f, 0.f, 0.f);
    #pragma unroll
    for (int s = 0; s < 8; s++) {
        int idx = s * 32 + lane;        // float4 index into the 32x32 tile
        float4 g4 = __ldg(&Grow[idx]);
        float4 p4 = __ldg(&pd4p[idx]);
        acc4.x = fmaf(__expf(-p4.x * t), g4.x, acc4.x);
        acc4.y = fmaf(__expf(-p4.y * t), g4.y, acc4.y);
        acc4.z = fmaf(__expf(-p4.z * t), g4.z, acc4.z);
        acc4.w = fmaf(__expf(-p4.w * t), g4.w, acc4.w);
    }

    // reduce over e: lanes {g, g+8, g+16, g+24} share the same c-group g=l&7
    #pragma unroll
    for (int d = 8; d <= 16; d <<= 1) {
        acc4.x += __shfl_xor_sync(0xffffffffu, acc4.x, d);
        acc4.y += __shfl_xor_sync(0xffffffffu, acc4.y, d);
        acc4.z += __shfl_xor_sync(0xffffffffu, acc4.z, d);
        acc4.w += __shfl_xor_sync(0xffffffffu, acc4.w, d);
    }

    // add mu for c-group g = lane&7
    float4 m4 = __ldg(&reinterpret_cast<const float4*>(g_sp_mu)[lane & 7]);
    acc4.x += m4.x; acc4.y += m4.y; acc4.z += m4.z; acc4.w += m4.w;

    // redistribute: lane c wants component c&3 from lane c>>2 (which holds
    // group g = c>>2 since (c>>2) < 8 and g = lane&7)
    int src = lane >> 2;
    float vx = __shfl_sync(0xffffffffu, acc4.x, src);
    float vy = __shfl_sync(0xffffffffu, acc4.y, src);
    float vz = __shfl_sync(0xffffffffu, acc4.z, src);
    float vw = __shfl_sync(0xffffffffu, acc4.w, src);
    int sel = lane & 3;
    float acc = (sel == 0) ? vx : (sel == 1) ? vy : (sel == 2) ? vz : vw;

    // Output: out[k] = acc[ftc[k]] * p[k], gather via shuffle (no smem)
    float* o = out + (size_t)warp_g * Kq;
    #pragma unroll
    for (int r = 0; r < 4; r++) {
        int   kk = r * 32 + lane;
        int   fc = __ldg(&ftc[kk]);
        float av = __shfl_sync(0xffffffffu, acc, fc);
        o[kk] = av * __ldg(&g_probs[kk]);
    }
}

// ---------------------------------------------------------------------------
// Launch: 2 graph-capturable kernel launches, no sync, no allocation.
// Input order (metadata): past_event, past_time, time_tensor, mu, alpha,
//                         delta, cf_logits, ftc
// ---------------------------------------------------------------------------
extern "C" void kernel_launch(void* const* d_in, const int* in_sizes, int n_in,
                              void* d_out, int out_size) {
    (void)in_sizes; (void)n_in; (void)out_size;
    const int*   past_event  = (const int*)  d_in[0];
    const float* past_time   = (const float*)d_in[1];
    const float* time_tensor = (const float*)d_in[2];
    const float* mu          = (const float*)d_in[3];
    const float* alpha       = (const float*)d_in[4];
    const float* delta       = (const float*)d_in[5];
    const float* cf          = (const float*)d_in[6];
    const int*   ftc         = (const int*)  d_in[7];
    float*       out         = (float*)d_out;

    table_kernel<<<Bq * Cq, 512>>>(past_event, past_time, alpha, delta, mu, cf, ftc);
    // 4096 queries, 1 warp each, 128-thread blocks -> 1024 blocks
    query_kernel<<<(Bq * TPq) / 4, 128>>>(time_tensor, past_time, ftc, out);
}

// round 9
// speedup vs baseline: 1.2333x; 1.2333x over previous
#include <cuda_runtime.h>

// Problem constants (fixed shapes from the reference setup_inputs)
#define Bq   4
#define Tq   512
#define TPq  1024
#define Cq   32
#define Kq   128
#define EPSF 2.2204460492503131e-16f

// Scratch (__device__ globals — no allocation allowed in kernel_launch)
__device__ float g_sp_delta[Cq * Cq];   // softplus(delta)[e][c] + EPS
__device__ float g_sp_mu[Cq];
__device__ float g_probs[Kq];           // p(fine k | coarse ftc[k])
// Prefix table: G[b][j][e][c], j in [0, T]  (8.4 MB, L2-resident)
__device__ float g_table[(size_t)Bq * (Tq + 1) * Cq * Cq];

__device__ __forceinline__ float softplus_f(float x) {
    // log(1 + e^x), fast version (rel err ~1e-6, tol is 1e-3)
    return (x > 0.0f) ? x + __logf(1.0f + __expf(-x))
                      : __logf(1.0f + __expf(x));
}

// ---------------------------------------------------------------------------
// Kernel 1: build causal prefix table + publish prepped parameters.
//   block = (b, e) pair, 512 threads = 16 warps; lane = channel c,
//   warp w owns j-chunk [w*32, (w+1)*32).
//   G[b][j][e][c] = sum over events i<j with type e of pa[e,c]*exp(pd[e,c]*pt_i)
//   Two-pass chunk scan: pass 1 chunk totals, pass 2 write prefix.
//   Side duties (prep):  b==0,wid==0: g_sp_delta row e
//                        block 0, wid 1: g_sp_mu;  wid 2: grouped softmax
// ---------------------------------------------------------------------------
__global__ void __launch_bounds__(512)
table_kernel(const int*   __restrict__ past_event,
             const float* __restrict__ past_time,
             const float* __restrict__ alpha,
             const float* __restrict__ delta,
             const float* __restrict__ mu,
             const float* __restrict__ cf,
             const int*   __restrict__ ftc) {
    int b   = blockIdx.x / Cq;
    int e   = blockIdx.x % Cq;
    int wid = threadIdx.x >> 5;
    int c   = threadIdx.x & 31;

    __shared__ int   s_ev[Tq];
    __shared__ float s_pt[Tq];
    __shared__ float s_chunk[16][Cq];
    __shared__ float s_den[Cq];

    for (int i = threadIdx.x; i < Tq; i += blockDim.x) {
        s_ev[i] = past_event[b * Tq + i];
        s_pt[i] = past_time[b * Tq + i];
    }

    float pa = softplus_f(alpha[e * Cq + c]);
    float pd = softplus_f(delta[e * Cq + c]) + EPSF;

    // ---- side duties (before first __syncthreads, fully parallel) ----
    if (b == 0 && wid == 0) g_sp_delta[e * Cq + c] = pd;
    if (blockIdx.x == 0) {
        if (wid == 1) g_sp_mu[c] = softplus_f(mu[c]);
        if (wid == 2) {
            // grouped softmax over 128 fine logits (max-shift cancels exactly)
            s_den[c] = 0.0f;
            __syncwarp();
            float ev[4]; int fc[4];
            #pragma unroll
            for (int r = 0; r < 4; r++) {
                int k = r * 32 + c;
                ev[r] = __expf(cf[k]);
                fc[r] = ftc[k];
                atomicAdd(&s_den[fc[r]], ev[r]);
            }
            __syncwarp();
            #pragma unroll
            for (int r = 0; r < 4; r++)
                g_probs[r * 32 + c] = ev[r] / s_den[fc[r]];
        }
    }
    __syncthreads();

    const int CHUNK = Tq / 16;          // 32
    int j0 = wid * CHUNK, j1 = j0 + CHUNK;

    // pass 1: chunk totals (s_ev[j]==e is warp-uniform -> exp only on matches)
    float sum = 0.0f;
    for (int j = j0; j < j1; j++)
        if (s_ev[j] == e) sum += pa * __expf(pd * s_pt[j]);
    s_chunk[wid][c] = sum;
    __syncthreads();

    float off = 0.0f;
    #pragma unroll
    for (int w = 0; w < 16; w++) if (w < wid) off += s_chunk[w][c];

    // pass 2: write exclusive prefix
    float* out = g_table + ((size_t)b * (Tq + 1)) * (Cq * Cq) + e * Cq + c;
    float run = off;
    for (int j = j0; j < j1; j++) {
        out[(size_t)j * (Cq * Cq)] = run;
        if (s_ev[j] == e) run += pa * __expf(pd * s_pt[j]);
    }
    if (wid == 15) out[(size_t)Tq * (Cq * Cq)] = run;
}

// ---------------------------------------------------------------------------
// Kernel 2: queries. One warp per query time. No shared memory, no barriers.
//   acc[c] = sp_mu[c] + sum_e exp(-pd[e,c]*t') * G[b][j][e][c]
//   j found by warp-parallel 2-round rank search (2 parallel load rounds
//   instead of a 9-step dependent binary search).
//   out[k] = acc[ftc[k]] * p[k] via shuffle gather.
// ---------------------------------------------------------------------------
__global__ void __launch_bounds__(128, 8)
query_kernel(const float* __restrict__ time_tensor,
             const float* __restrict__ past_time,
             const int*   __restrict__ ftc,
             float*       __restrict__ out) {
    int warp_g = (blockIdx.x * blockDim.x + threadIdx.x) >> 5;  // global query id
    int lane   = threadIdx.x & 31;
    int b      = warp_g >> 10;          // / TPq

    float t = time_tensor[warp_g];

    // --- warp-parallel rank: j = #{i : t - pt_i > EPS} (pt non-decreasing,
    //     so the predicate is true exactly on a prefix i < j) ---
    const float* pt = past_time + b * Tq;
    // round 1: lane l tests the LAST element of 16-element chunk l.
    //   chunk l is fully-true iff pred(16l+15); full = count of such chunks.
    float v1 = __ldg(&pt[lane * 16 + 15]);
    unsigned m1 = __ballot_sync(0xffffffffu, t - v1 > EPSF);
    int full = __popc(m1);
    int j = full * 16;
    if (full < 32) {
        // round 2: lanes 0..15 test the partial chunk 'full'
        float v2 = __ldg(&pt[full * 16 + (lane & 15)]);
        bool p2 = (lane < 16) && (t - v2 > EPSF);
        j += __popc(__ballot_sync(0xffffffffu, p2));
    }

    // Precompute all 32 decay factors (independent MUFU ops — overlap search)
    float ex[Cq];
    #pragma unroll
    for (int e = 0; e < Cq; e++)
        ex[e] = __expf(-__ldg(&g_sp_delta[e * Cq + lane]) * t);

    const float* Grow = g_table + ((size_t)(b * (Tq + 1) + j)) * (Cq * Cq);

    // 32 independent coalesced L2 loads + 4-way FMA trees
    float a0 = 0.0f, a1 = 0.0f, a2 = 0.0f, a3 = 0.0f;
    #pragma unroll
    for (int e = 0; e < Cq; e += 4) {
        a0 = fmaf(ex[e + 0], __ldg(&Grow[(e + 0) * Cq + lane]), a0);
        a1 = fmaf(ex[e + 1], __ldg(&Grow[(e + 1) * Cq + lane]), a1);
        a2 = fmaf(ex[e + 2], __ldg(&Grow[(e + 2) * Cq + lane]), a2);
        a3 = fmaf(ex[e + 3], __ldg(&Grow[(e + 3) * Cq + lane]), a3);
    }
    float acc = ((a0 + a1) + (a2 + a3)) + __ldg(&g_sp_mu[lane]);

    // Output: out[k] = acc[ftc[k]] * p[k], gather via shuffle (no smem)
    float* o = out + (size_t)warp_g * Kq;
    #pragma unroll
    for (int r = 0; r < 4; r++) {
        int   kk = r * 32 + lane;
        int   fc = __ldg(&ftc[kk]);
        float av = __shfl_sync(0xffffffffu, acc, fc);
        o[kk] = av * __ldg(&g_probs[kk]);
    }
}

// ---------------------------------------------------------------------------
// Launch: 2 graph-capturable kernel launches, no sync, no allocation.
// Input order (metadata): past_event, past_time, time_tensor, mu, alpha,
//                         delta, cf_logits, ftc
// ---------------------------------------------------------------------------
extern "C" void kernel_launch(void* const* d_in, const int* in_sizes, int n_in,
                              void* d_out, int out_size) {
    (void)in_sizes; (void)n_in; (void)out_size;
    const int*   past_event  = (const int*)  d_in[0];
    const float* past_time   = (const float*)d_in[1];
    const float* time_tensor = (const float*)d_in[2];
    const float* mu          = (const float*)d_in[3];
    const float* alpha       = (const float*)d_in[4];
    const float* delta       = (const float*)d_in[5];
    const float* cf          = (const float*)d_in[6];
    const int*   ftc         = (const int*)  d_in[7];
    float*       out         = (float*)d_out;

    table_kernel<<<Bq * Cq, 512>>>(past_event, past_time, alpha, delta, mu, cf, ftc);
    // 4096 queries, 1 warp each, 128-thread blocks -> 1024 blocks
    query_kernel<<<(Bq * TPq) / 4, 128>>>(time_tensor, past_time, ftc, out);
}